// round 15
// baseline (speedup 1.0000x reference)
#include <cuda_runtime.h>
#include <cuda_fp16.h>
#include <cstdint>

// SoftCountPixels: Y[b,p] = (1/(H*W)) * sum_{h,w} exp(-||x[b,:,h,w] - P[p,:]||_2 / 0.6)
// x: (16, 3, 256, 256) f32 planar; P: (32, 3) f32; out: (16, 32) f32
//
// exp(-d/0.6) = ex2(-sqrt(K2*d^2)), K2=(log2e/0.6)^2 (pre-scaled quadratic form,
// eps-biased so s>0 -> no fabs). EX2 via ex2.approx.f16x2 (2 exps / MUFU op).
// R15: SCALAR quadratic form. Evidence across rounds shows ptxas splits
// fma.rn.f32x2 into two scalar FFMAs on this target (fma% identical between
// scalar and packed variants), so the f32x2 layer only added unpack movs and
// 64-bit register-pairing pressure. Scalar math = same FFMA count, fewer movs,
// freer scheduling. Everything else keeps the verified-best config:
// f16x2 EX2 epilogue, 592 balanced blocks @ 4 CTA/SM, scratch+ticket launch.

#define B 16
#define HW (256 * 256)
#define HW4 (HW / 4)             // 16384 = 2^14 vec4 per channel plane
#define HW4_SHIFT 14
#define NPRO 32
#define PPT 4                    // protos per thread
#define PGROUPS (NPRO / PPT)     // 8
#define NCOMBO (B * PGROUPS)     // 128
#define THREADS 256
#define NBLOCKS (148 * 4)        // 592: one perfectly balanced wave @ 4 CTA/SM
#define TOTAL_UNITS ((unsigned long long)NCOMBO * HW4)   // 2,097,152

#define K2 5.781580510735007f    // (log2(e)/0.6)^2
#define EPS_S 3e-5f              // positivity guard for the quadratic form

__device__ float    g_scratch[B * NPRO];   // zero-initialized at module load
__device__ unsigned g_ticket = 0;

__device__ __forceinline__ float fast_sqrt(float v) {
    float r;
    asm("sqrt.approx.f32 %0, %1;" : "=f"(r) : "f"(v));
    return r;
}
// pack two f32 into f16x2 (one F2FP)
__device__ __forceinline__ uint32_t cvt_f16x2(float lo, float hi) {
    uint32_t h;
    asm("cvt.rn.f16x2.f32 %0, %1, %2;" : "=r"(h) : "f"(hi), "f"(lo));
    return h;
}
// two exponentials in ONE MUFU op
__device__ __forceinline__ uint32_t ex2_h2(uint32_t h) {
    uint32_t e;
    asm("ex2.approx.f16x2 %0, %1;" : "=r"(e) : "r"(h));
    return e;
}
__device__ __forceinline__ uint32_t hadd2u(uint32_t a, uint32_t b) {
    uint32_t r;
    asm("add.rn.f16x2 %0, %1, %2;" : "=r"(r) : "r"(a), "r"(b));
    return r;
}

// quadratic form for one (pixel, proto) pair: s = cck + xxk + q.x  (4 fma-pipe ops)
__device__ __forceinline__ float qform(float cxk, float q0, float q1, float q2,
                                       float x0, float x1, float x2) {
    float t = fmaf(q0, x0, cxk);
    t = fmaf(q1, x1, t);
    t = fmaf(q2, x2, t);
    return t;
}

__global__ __launch_bounds__(THREADS, 4)
void softcount_kernel(const float* __restrict__ x,
                      const float* __restrict__ P,
                      float* __restrict__ out) {
    const int tid  = threadIdx.x;
    const int lane = tid & 31;
    const unsigned long long bid = blockIdx.x;

    // This block's contiguous range of global vec4-units.
    unsigned long long u0 = (bid * TOTAL_UNITS) / NBLOCKS;
    const unsigned long long u1 = ((bid + 1) * TOTAL_UNITS) / NBLOCKS;

    while (u0 < u1) {
        const unsigned combo = (unsigned)(u0 >> HW4_SHIFT);   // 0..127
        const unsigned long long combo_end = (unsigned long long)(combo + 1) << HW4_SHIFT;
        const unsigned long long seg_end = (u1 < combo_end) ? u1 : combo_end;

        const int pg = (int)(combo >> 4);   // 0..7
        const int b  = (int)(combo & 15);   // 0..15

        // Scalar per-proto constants, pre-scaled by K2, eps-biased.
        float q0[PPT], q1[PPT], q2[PPT], cck[PPT];
        uint32_t hacc[PPT];                 // half2 accumulators
#pragma unroll
        for (int i = 0; i < PPT; i++) {
            const int p = pg * PPT + i;
            const float p0 = __ldg(&P[p * 3 + 0]);
            const float p1 = __ldg(&P[p * 3 + 1]);
            const float p2 = __ldg(&P[p * 3 + 2]);
            q0[i] = -2.0f * K2 * p0;
            q1[i] = -2.0f * K2 * p1;
            q2[i] = -2.0f * K2 * p2;
            cck[i] = K2 * (p0 * p0 + p1 * p1 + p2 * p2) + EPS_S;
            hacc[i] = 0u;
        }

        // Local vec4 index range within this combo's image.
        const int vs = (int)(u0 & (HW4 - 1));
        const int ve = (int)(seg_end - ((unsigned long long)combo << HW4_SHIFT));

        const float4* xb = (const float4*)(x + (size_t)b * 3 * HW);

        for (int v = vs + tid; v < ve; v += THREADS) {
            const float4 c0 = xb[v];              // channel 0, pixels 0..3
            const float4 c1 = xb[v + HW4];        // channel 1
            const float4 c2 = xb[v + 2 * HW4];    // channel 2

            // per-pixel K2*||x||^2
            float xxk0 = K2 * (fmaf(c2.x, c2.x, fmaf(c1.x, c1.x, c0.x * c0.x)));
            float xxk1 = K2 * (fmaf(c2.y, c2.y, fmaf(c1.y, c1.y, c0.y * c0.y)));
            float xxk2 = K2 * (fmaf(c2.z, c2.z, fmaf(c1.z, c1.z, c0.z * c0.z)));
            float xxk3 = K2 * (fmaf(c2.w, c2.w, fmaf(c1.w, c1.w, c0.w * c0.w)));

#pragma unroll
            for (int i = 0; i < PPT; i++) {
                const float cx0 = cck[i] + xxk0;
                const float cx1 = cck[i] + xxk1;
                const float cx2 = cck[i] + xxk2;
                const float cx3 = cck[i] + xxk3;
                const float sa = qform(cx0, q0[i], q1[i], q2[i], c0.x, c1.x, c2.x);
                const float sb = qform(cx1, q0[i], q1[i], q2[i], c0.y, c1.y, c2.y);
                const float sc = qform(cx2, q0[i], q1[i], q2[i], c0.z, c1.z, c2.z);
                const float sd = qform(cx3, q0[i], q1[i], q2[i], c0.w, c1.w, c2.w);
                const float ra = fast_sqrt(sa);   // MUFU.SQRT x4
                const float rb = fast_sqrt(sb);
                const float rc = fast_sqrt(sc);
                const float rd = fast_sqrt(sd);
                uint32_t hab = cvt_f16x2(ra, rb) ^ 0x80008000u;  // pack + negate
                uint32_t hcd = cvt_f16x2(rc, rd) ^ 0x80008000u;
                hacc[i] = hadd2u(hacc[i], ex2_h2(hab));          // 2 exps / MUFU
                hacc[i] = hadd2u(hacc[i], ex2_h2(hcd));
            }
        }

        // Flush this segment into scratch: half2 -> f32, warp shuffle,
        // 1 atomic per (warp, proto).
#pragma unroll
        for (int i = 0; i < PPT; i++) {
            const __half2 h = *reinterpret_cast<const __half2*>(&hacc[i]);
            const float2 f = __half22float2(h);
            float v = f.x + f.y;
#pragma unroll
            for (int off = 16; off > 0; off >>= 1)
                v += __shfl_xor_sync(0xFFFFFFFFu, v, off);
            if (lane == 0)
                atomicAdd(&g_scratch[b * NPRO + pg * PPT + i], v);
        }

        u0 = seg_end;
    }

    // ---- last-block finisher: scale scratch into d_out, reset state ----
    __threadfence();
    __shared__ unsigned is_last;
    if (tid == 0) {
        const unsigned t = atomicAdd(&g_ticket, 1u);
        is_last = (t == NBLOCKS - 1) ? 1u : 0u;
    }
    __syncthreads();
    if (is_last) {
        __threadfence();  // all blocks' scratch atomics visible
        for (int i = tid; i < B * NPRO; i += THREADS) {
            out[i] = g_scratch[i] * (1.0f / (float)HW);
            g_scratch[i] = 0.0f;          // reset for next graph replay
        }
        __syncthreads();
        if (tid == 0) g_ticket = 0u;      // reset ticket
    }
}

extern "C" void kernel_launch(void* const* d_in, const int* in_sizes, int n_in,
                              void* d_out, int out_size) {
    const float* x = (const float*)d_in[0];
    const float* P = (const float*)d_in[1];
    float* out = (float*)d_out;

    softcount_kernel<<<NBLOCKS, THREADS>>>(x, P, out);
}

// round 16
// speedup vs baseline: 1.0875x; 1.0875x over previous
#include <cuda_runtime.h>
#include <cuda_fp16.h>
#include <cstdint>

// SoftCountPixels: Y[b,p] = (1/(H*W)) * sum_{h,w} exp(-||x[b,:,h,w] - P[p,:]||_2 / 0.6)
// x: (16, 3, 256, 256) f32 planar; P: (32, 3) f32; out: (16, 32) f32
//
// exp(-d/0.6) = ex2(-sqrt(K2*d^2)), K2=(log2e/0.6)^2 (pre-scaled f32x2 quadratic
// form, eps-biased so s>0 -> no fabs). EX2 via ex2.approx.f16x2 (2 exps / MUFU).
// R16 ONE CHANGE vs R12 (best, 21.4us): PPT 4->2 and 5 CTAs/SM. The kernel is
// latency-bound on per-warp dependency chains (no port >54%); halving per-thread
// proto state frees registers for a 5th resident CTA -> 10 warps/SMSP.
// Cost: x re-read 16x (~201MB, L2-resident; L2 was at 15% -> headroom).

#define B 16
#define HW (256 * 256)
#define HW4 (HW / 4)             // 16384 = 2^14 vec4 per channel plane
#define HW4_SHIFT 14
#define NPRO 32
#define PPT 2                    // protos per thread
#define PGROUPS (NPRO / PPT)     // 16
#define NCOMBO (B * PGROUPS)     // 256
#define THREADS 256
#define NBLOCKS (148 * 5)        // 740: one perfectly balanced wave @ 5 CTA/SM
#define TOTAL_UNITS ((unsigned long long)NCOMBO * HW4)   // 4,194,304

#define K2 5.781580510735007f    // (log2(e)/0.6)^2
#define EPS_S 3e-5f              // positivity guard for the quadratic form

__device__ float    g_scratch[B * NPRO];   // zero-initialized at module load
__device__ unsigned g_ticket = 0;

__device__ __forceinline__ float fast_sqrt(float v) {
    float r;
    asm("sqrt.approx.f32 %0, %1;" : "=f"(r) : "f"(v));
    return r;
}
__device__ __forceinline__ uint32_t cvt_f16x2(float lo, float hi) {
    uint32_t h;
    asm("cvt.rn.f16x2.f32 %0, %1, %2;" : "=r"(h) : "f"(hi), "f"(lo));
    return h;
}
__device__ __forceinline__ uint32_t ex2_h2(uint32_t h) {
    uint32_t e;
    asm("ex2.approx.f16x2 %0, %1;" : "=r"(e) : "r"(h));
    return e;
}
__device__ __forceinline__ uint32_t hadd2u(uint32_t a, uint32_t b) {
    uint32_t r;
    asm("add.rn.f16x2 %0, %1, %2;" : "=r"(r) : "r"(a), "r"(b));
    return r;
}

// ---- packed f32x2 helpers ----
__device__ __forceinline__ uint64_t pack2(float lo, float hi) {
    uint64_t r;
    asm("mov.b64 %0, {%1, %2};" : "=l"(r) : "f"(lo), "f"(hi));
    return r;
}
__device__ __forceinline__ void unpack2(uint64_t v, float& lo, float& hi) {
    asm("mov.b64 {%0, %1}, %2;" : "=f"(lo), "=f"(hi) : "l"(v));
}
__device__ __forceinline__ uint64_t fma2(uint64_t a, uint64_t b, uint64_t c) {
    uint64_t r;
    asm("fma.rn.f32x2 %0, %1, %2, %3;" : "=l"(r) : "l"(a), "l"(b), "l"(c));
    return r;
}
__device__ __forceinline__ uint64_t add2(uint64_t a, uint64_t b) {
    uint64_t r;
    asm("add.rn.f32x2 %0, %1, %2;" : "=l"(r) : "l"(a), "l"(b));
    return r;
}
__device__ __forceinline__ uint64_t mul2(uint64_t a, uint64_t b) {
    uint64_t r;
    asm("mul.rn.f32x2 %0, %1, %2;" : "=l"(r) : "l"(a), "l"(b));
    return r;
}

__global__ __launch_bounds__(THREADS, 5)
void softcount_kernel(const float* __restrict__ x,
                      const float* __restrict__ P,
                      float* __restrict__ out) {
    const int tid  = threadIdx.x;
    const int lane = tid & 31;
    const unsigned long long bid = blockIdx.x;

    // This block's contiguous range of global vec4-units.
    unsigned long long u0 = (bid * TOTAL_UNITS) / NBLOCKS;
    const unsigned long long u1 = ((bid + 1) * TOTAL_UNITS) / NBLOCKS;

    while (u0 < u1) {
        const unsigned combo = (unsigned)(u0 >> HW4_SHIFT);   // 0..255
        const unsigned long long combo_end = (unsigned long long)(combo + 1) << HW4_SHIFT;
        const unsigned long long seg_end = (u1 < combo_end) ? u1 : combo_end;

        const int pg = (int)(combo >> 4);   // 0..15
        const int b  = (int)(combo & 15);   // 0..15

        // Packed (broadcast) per-proto constants, pre-scaled by K2, eps-biased.
        uint64_t qk0[PPT], qk1[PPT], qk2[PPT], cck[PPT];
        uint32_t hacc[PPT];                 // half2 accumulators
#pragma unroll
        for (int i = 0; i < PPT; i++) {
            const int p = pg * PPT + i;
            const float p0 = __ldg(&P[p * 3 + 0]);
            const float p1 = __ldg(&P[p * 3 + 1]);
            const float p2 = __ldg(&P[p * 3 + 2]);
            const float q0 = -2.0f * K2 * p0;
            const float q1 = -2.0f * K2 * p1;
            const float q2 = -2.0f * K2 * p2;
            const float cc = K2 * (p0 * p0 + p1 * p1 + p2 * p2) + EPS_S;
            qk0[i] = pack2(q0, q0);
            qk1[i] = pack2(q1, q1);
            qk2[i] = pack2(q2, q2);
            cck[i] = pack2(cc, cc);
            hacc[i] = 0u;
        }
        const uint64_t K2_2 = pack2(K2, K2);

        // Local vec4 index range within this combo's image.
        const int vs = (int)(u0 & (HW4 - 1));
        const int ve = (int)(seg_end - ((unsigned long long)combo << HW4_SHIFT));

        const ulonglong2* xb = (const ulonglong2*)(x + (size_t)b * 3 * HW);

        for (int v = vs + tid; v < ve; v += THREADS) {
            const ulonglong2 c0 = xb[v];              // ch0: pixels(0,1),(2,3) packed
            const ulonglong2 c1 = xb[v + HW4];        // ch1
            const ulonglong2 c2 = xb[v + 2 * HW4];    // ch2

            // ---- pixel pair (0,1) ----
            {
                const uint64_t X0 = c0.x, X1 = c1.x, X2 = c2.x;
                uint64_t xx = mul2(X0, X0);
                xx = fma2(X1, X1, xx);
                xx = fma2(X2, X2, xx);
                const uint64_t xxk = mul2(K2_2, xx);
#pragma unroll
                for (int i = 0; i < PPT; i++) {
                    uint64_t t = add2(cck[i], xxk);
                    t = fma2(qk0[i], X0, t);
                    t = fma2(qk1[i], X1, t);
                    t = fma2(qk2[i], X2, t);
                    float ta, tb;
                    unpack2(t, ta, tb);
                    const float ra = fast_sqrt(ta);        // MUFU.SQRT
                    const float rb = fast_sqrt(tb);        // MUFU.SQRT
                    uint32_t h = cvt_f16x2(ra, rb);        // F2FP pack
                    h ^= 0x80008000u;                      // negate both halves
                    hacc[i] = hadd2u(hacc[i], ex2_h2(h));  // ONE MUFU EX2 + HADD2
                }
            }
            // ---- pixel pair (2,3) ----
            {
                const uint64_t X0 = c0.y, X1 = c1.y, X2 = c2.y;
                uint64_t xx = mul2(X0, X0);
                xx = fma2(X1, X1, xx);
                xx = fma2(X2, X2, xx);
                const uint64_t xxk = mul2(K2_2, xx);
#pragma unroll
                for (int i = 0; i < PPT; i++) {
                    uint64_t t = add2(cck[i], xxk);
                    t = fma2(qk0[i], X0, t);
                    t = fma2(qk1[i], X1, t);
                    t = fma2(qk2[i], X2, t);
                    float ta, tb;
                    unpack2(t, ta, tb);
                    const float ra = fast_sqrt(ta);
                    const float rb = fast_sqrt(tb);
                    uint32_t h = cvt_f16x2(ra, rb);
                    h ^= 0x80008000u;
                    hacc[i] = hadd2u(hacc[i], ex2_h2(h));
                }
            }
        }

        // Flush this segment into scratch: half2 -> f32, warp shuffle,
        // 1 atomic per (warp, proto).
#pragma unroll
        for (int i = 0; i < PPT; i++) {
            const __half2 h = *reinterpret_cast<const __half2*>(&hacc[i]);
            const float2 f = __half22float2(h);
            float v = f.x + f.y;
#pragma unroll
            for (int off = 16; off > 0; off >>= 1)
                v += __shfl_xor_sync(0xFFFFFFFFu, v, off);
            if (lane == 0)
                atomicAdd(&g_scratch[b * NPRO + pg * PPT + i], v);
        }

        u0 = seg_end;
    }

    // ---- last-block finisher: scale scratch into d_out, reset state ----
    __threadfence();
    __shared__ unsigned is_last;
    if (tid == 0) {
        const unsigned t = atomicAdd(&g_ticket, 1u);
        is_last = (t == NBLOCKS - 1) ? 1u : 0u;
    }
    __syncthreads();
    if (is_last) {
        __threadfence();  // all blocks' scratch atomics visible
        for (int i = tid; i < B * NPRO; i += THREADS) {
            out[i] = g_scratch[i] * (1.0f / (float)HW);
            g_scratch[i] = 0.0f;          // reset for next graph replay
        }
        __syncthreads();
        if (tid == 0) g_ticket = 0u;      // reset ticket
    }
}

extern "C" void kernel_launch(void* const* d_in, const int* in_sizes, int n_in,
                              void* d_out, int out_size) {
    const float* x = (const float*)d_in[0];
    const float* P = (const float*)d_in[1];
    float* out = (float*)d_out;

    softcount_kernel<<<NBLOCKS, THREADS>>>(x, P, out);
}